// round 6
// baseline (speedup 1.0000x reference)
#include <cuda_runtime.h>
#include <math.h>
#include <stdint.h>

#define BQ 2
#define HH 16
#define SS 2048
#define DK 64
#define DM 1024
#define MTOT (BQ*SS)   // 4096

__device__ float g_qh[BQ*HH*SS*DK];
__device__ float g_kh[BQ*HH*SS*DK];
__device__ float g_vh[BQ*HH*SS*DK];
__device__ float g_ctx[BQ*SS*DM];

// ---------------------------------------------------------------------------
__device__ __forceinline__ uint32_t f2tf(float x) {
    uint32_t u;
    asm("cvt.rna.tf32.f32 %0, %1;" : "=r"(u) : "f"(x));
    return u;
}

__device__ __forceinline__ void mma8(float4& d,
                                     uint32_t a0, uint32_t a1, uint32_t a2, uint32_t a3,
                                     uint32_t b0, uint32_t b1) {
    asm volatile(
        "mma.sync.aligned.m16n8k8.row.col.f32.tf32.tf32.f32 "
        "{%0,%1,%2,%3},{%4,%5,%6,%7},{%8,%9},{%0,%1,%2,%3};"
        : "+f"(d.x), "+f"(d.y), "+f"(d.z), "+f"(d.w)
        : "r"(a0), "r"(a1), "r"(a2), "r"(a3), "r"(b0), "r"(b1));
}

__device__ __forceinline__ void cp16(float* sdst, const float* gsrc) {
    uint32_t sa = (uint32_t)__cvta_generic_to_shared(sdst);
    asm volatile("cp.async.cg.shared.global [%0], [%1], 16;" :: "r"(sa), "l"(gsrc) : "memory");
}
#define CP_COMMIT() asm volatile("cp.async.commit_group;" ::: "memory")
#define CP_WAIT1()  asm volatile("cp.async.wait_group 1;" ::: "memory")
#define CP_WAIT0()  asm volatile("cp.async.wait_group 0;" ::: "memory")

// ---------------------------------------------------------------------------
// Fused QKV projection GEMM (unchanged from R4/5 win)
// ---------------------------------------------------------------------------
#define A_STRIDE 36
#define B_STRIDE 136
#define A_TILE (128*A_STRIDE)
#define B_TILE (32*B_STRIDE)

__global__ __launch_bounds__(256) void proj_gemm(
    const float* __restrict__ Xq, const float* __restrict__ Xk, const float* __restrict__ Xv,
    const float* __restrict__ Wq, const float* __restrict__ Wk, const float* __restrict__ Wv,
    float* __restrict__ Oq, float* __restrict__ Ok, float* __restrict__ Ov)
{
    extern __shared__ float sm[];
    float* As = sm;
    float* Bs = sm + 2*A_TILE;

    const int z = blockIdx.z;
    const float* X = (z == 0) ? Xq : (z == 1) ? Xk : Xv;
    const float* W = (z == 0) ? Wq : (z == 1) ? Wk : Wv;
    float* out     = (z == 0) ? Oq : (z == 1) ? Ok : Ov;

    const int tid = threadIdx.x, lane = tid & 31, warp = tid >> 5;
    const int gid = lane >> 2, tig = lane & 3;
    const int wm = (warp >> 2) * 64, wn = (warp & 3) * 32;
    const int m0 = blockIdx.x * 128, n0 = blockIdx.y * 128;

    float4 acc[4][4];
    #pragma unroll
    for (int i = 0; i < 4; i++)
        #pragma unroll
        for (int j = 0; j < 4; j++) acc[i][j] = make_float4(0.f, 0.f, 0.f, 0.f);

    auto stage = [&](int buf, int k0) {
        float* Ab = As + buf*A_TILE;
        float* Bb = Bs + buf*B_TILE;
        #pragma unroll
        for (int i = 0; i < 4; i++) {
            int f = tid + i*256;
            int r = f >> 3, c = f & 7;
            cp16(&Ab[r*A_STRIDE + c*4], &X[(size_t)(m0 + r)*DM + k0 + c*4]);
        }
        #pragma unroll
        for (int i = 0; i < 4; i++) {
            int f = tid + i*256;
            int r = f >> 5, c = f & 31;
            int n = n0 + c*4;
            int h = n >> 6, kc = n & 63;
            cp16(&Bb[r*B_STRIDE + c*4], &W[((size_t)h*DM + k0 + r)*DK + kc]);
        }
    };

    stage(0, 0);  CP_COMMIT();
    stage(1, 32); CP_COMMIT();

    #pragma unroll 1
    for (int k0 = 0; k0 < DM; k0 += 32) {
        int buf = (k0 >> 5) & 1;
        CP_WAIT1();
        __syncthreads();
        const float* Ab = As + buf*A_TILE;
        const float* Bb = Bs + buf*B_TILE;

        #pragma unroll
        for (int kk = 0; kk < 32; kk += 8) {
            uint32_t a[4][4];
            #pragma unroll
            for (int i = 0; i < 4; i++) {
                int ra = (wm + i*16 + gid)*A_STRIDE + kk + tig;
                a[i][0] = f2tf(Ab[ra]);
                a[i][1] = f2tf(Ab[ra + 8*A_STRIDE]);
                a[i][2] = f2tf(Ab[ra + 4]);
                a[i][3] = f2tf(Ab[ra + 8*A_STRIDE + 4]);
            }
            uint32_t b[4][2];
            #pragma unroll
            for (int j = 0; j < 4; j++) {
                int rb = (kk + tig)*B_STRIDE + wn + j*8 + gid;
                b[j][0] = f2tf(Bb[rb]);
                b[j][1] = f2tf(Bb[rb + 4*B_STRIDE]);
            }
            #pragma unroll
            for (int i = 0; i < 4; i++)
                #pragma unroll
                for (int j = 0; j < 4; j++)
                    mma8(acc[i][j], a[i][0], a[i][1], a[i][2], a[i][3], b[j][0], b[j][1]);
        }
        __syncthreads();
        if (k0 + 64 < DM) stage(buf, k0 + 64);
        CP_COMMIT();
    }

    #pragma unroll
    for (int i = 0; i < 4; i++) {
        int r0 = m0 + wm + i*16 + gid, r1 = r0 + 8;
        int b0i = r0 >> 11, s0 = r0 & 2047;
        int b1i = r1 >> 11, s1 = r1 & 2047;
        #pragma unroll
        for (int j = 0; j < 4; j++) {
            int c = n0 + wn + j*8 + tig*2;
            int h = c >> 6, kc = c & 63;
            *reinterpret_cast<float2*>(&out[(((size_t)b0i*HH + h)*SS + s0)*DK + kc]) =
                make_float2(acc[i][j].x, acc[i][j].y);
            *reinterpret_cast<float2*>(&out[(((size_t)b1i*HH + h)*SS + s1)*DK + kc]) =
                make_float2(acc[i][j].z, acc[i][j].w);
        }
    }
}

// ---------------------------------------------------------------------------
// Output projection GEMM (unchanged)
// ---------------------------------------------------------------------------
__global__ __launch_bounds__(256) void outproj_gemm(
    const float* __restrict__ X, const float* __restrict__ Wo,
    const float* __restrict__ bo, float* __restrict__ out)
{
    extern __shared__ float sm[];
    float* As = sm;
    float* Bt = sm + 2*A_TILE;

    const int tid = threadIdx.x, lane = tid & 31, warp = tid >> 5;
    const int gid = lane >> 2, tig = lane & 3;
    const int wm = (warp >> 2) * 64, wn = (warp & 3) * 32;
    const int m0 = blockIdx.x * 128, n0 = blockIdx.y * 128;

    float4 acc[4][4];
    #pragma unroll
    for (int i = 0; i < 4; i++)
        #pragma unroll
        for (int j = 0; j < 4; j++) acc[i][j] = make_float4(0.f, 0.f, 0.f, 0.f);

    auto stage = [&](int buf, int k0) {
        float* Ab = As + buf*A_TILE;
        float* Bb = Bt + buf*A_TILE;
        #pragma unroll
        for (int i = 0; i < 4; i++) {
            int f = tid + i*256;
            int r = f >> 3, c = f & 7;
            cp16(&Ab[r*A_STRIDE + c*4], &X[(size_t)(m0 + r)*DM + k0 + c*4]);
            cp16(&Bb[r*A_STRIDE + c*4], &Wo[(size_t)(n0 + r)*DM + k0 + c*4]);
        }
    };

    stage(0, 0);  CP_COMMIT();
    stage(1, 32); CP_COMMIT();

    #pragma unroll 1
    for (int k0 = 0; k0 < DM; k0 += 32) {
        int buf = (k0 >> 5) & 1;
        CP_WAIT1();
        __syncthreads();
        const float* Ab = As + buf*A_TILE;
        const float* Bb = Bt + buf*A_TILE;

        #pragma unroll
        for (int kk = 0; kk < 32; kk += 8) {
            uint32_t a[4][4];
            #pragma unroll
            for (int i = 0; i < 4; i++) {
                int ra = (wm + i*16 + gid)*A_STRIDE + kk + tig;
                a[i][0] = f2tf(Ab[ra]);
                a[i][1] = f2tf(Ab[ra + 8*A_STRIDE]);
                a[i][2] = f2tf(Ab[ra + 4]);
                a[i][3] = f2tf(Ab[ra + 8*A_STRIDE + 4]);
            }
            uint32_t b[4][2];
            #pragma unroll
            for (int j = 0; j < 4; j++) {
                int rb = (wn + j*8 + gid)*A_STRIDE + kk + tig;
                b[j][0] = f2tf(Bb[rb]);
                b[j][1] = f2tf(Bb[rb + 4]);
            }
            #pragma unroll
            for (int i = 0; i < 4; i++)
                #pragma unroll
                for (int j = 0; j < 4; j++)
                    mma8(acc[i][j], a[i][0], a[i][1], a[i][2], a[i][3], b[j][0], b[j][1]);
        }
        __syncthreads();
        if (k0 + 64 < DM) stage(buf, k0 + 64);
        CP_COMMIT();
    }

    #pragma unroll
    for (int i = 0; i < 4; i++) {
        int r0 = m0 + wm + i*16 + gid, r1 = r0 + 8;
        #pragma unroll
        for (int j = 0; j < 4; j++) {
            int c = n0 + wn + j*8 + tig*2;
            float bx = bo[c], by = bo[c + 1];
            *reinterpret_cast<float2*>(&out[(size_t)r0*DM + c]) =
                make_float2(acc[i][j].x + bx, acc[i][j].y + by);
            *reinterpret_cast<float2*>(&out[(size_t)r1*DM + c]) =
                make_float2(acc[i][j].z + bx, acc[i][j].w + by);
        }
    }
}

// ---------------------------------------------------------------------------
// Flash attention v4: cp.async double-buffered raw K/V + deferred tf32 convert.
// 128 q-rows/CTA, 64-key chunks, 8 warps.
// smem: raw fp32 2 x [64][128] (K|V), tf32 Ks[64x68], Vs[64x72]. 101376 B.
// ---------------------------------------------------------------------------
#define RAW_TILE 8192   // floats per raw buffer (64 rows x 128 cols)
#define NCHUNK (SS/64)

__global__ __launch_bounds__(256, 2) void attn4(
    const float* __restrict__ Q, const float* __restrict__ K,
    const float* __restrict__ V, float* __restrict__ ctx)
{
    extern __shared__ float smf[];
    float* raw = smf;                                        // 2 x 8192 floats
    uint32_t* Ks = reinterpret_cast<uint32_t*>(smf) + 2*RAW_TILE;  // 64 x 68
    uint32_t* Vs = Ks + 64*68;                               // 64 x 72

    const int tid = threadIdx.x, lane = tid & 31, warp = tid >> 5;
    const int gid = lane >> 2, tig = lane & 3;
    const int wr = warp * 16;
    const int q0 = blockIdx.x * 128;
    const int bh = blockIdx.y;
    const unsigned FULL = 0xffffffffu;

    const float* Qb = Q + (size_t)bh * SS * DK;
    const float* Kb = K + (size_t)bh * SS * DK;
    const float* Vb = V + (size_t)bh * SS * DK;

    auto stage_raw = [&](int buf, int j0) {
        float* rb = raw + buf*RAW_TILE;
        #pragma unroll
        for (int i = 0; i < 8; i++) {
            int f = tid + i*256;
            int r = f >> 5, c = f & 31;
            const float* src = (c < 16) ? &Kb[(size_t)(j0 + r)*DK + c*4]
                                        : &Vb[(size_t)(j0 + r)*DK + (c - 16)*4];
            cp16(&rb[r*128 + c*4], src);
        }
    };
    auto cvt_pass = [&](int buf) {
        const float* rb = raw + buf*RAW_TILE;
        #pragma unroll
        for (int i = 0; i < 8; i++) {
            int f = tid + i*256;
            int r = f >> 5, c = f & 31;
            float4 v = *reinterpret_cast<const float4*>(&rb[r*128 + c*4]);
            uint4 t = make_uint4(f2tf(v.x), f2tf(v.y), f2tf(v.z), f2tf(v.w));
            if (c < 16) *reinterpret_cast<uint4*>(&Ks[r*68 + c*4]) = t;
            else        *reinterpret_cast<uint4*>(&Vs[r*72 + (c - 16)*4]) = t;
        }
    };

    // Prologue: start chunk-0 raw load, stage Q (scaled, tf32) into Ks region,
    // lift Q fragments to registers, then convert chunk 0.
    stage_raw(0, 0);
    CP_COMMIT();

    uint32_t* Qs = Ks;   // 128 rows x stride 68 fits in Ks+Vs region (8704 <= 8960)
    #pragma unroll
    for (int i = 0; i < 8; i++) {
        int f = tid + i*256;
        int r = f >> 4, c4 = f & 15;
        float4 v = *reinterpret_cast<const float4*>(&Qb[(size_t)(q0 + r)*DK + c4*4]);
        uint4 t = make_uint4(f2tf(v.x*0.125f), f2tf(v.y*0.125f),
                             f2tf(v.z*0.125f), f2tf(v.w*0.125f));
        *reinterpret_cast<uint4*>(&Qs[r*68 + c4*4]) = t;
    }
    __syncthreads();
    uint32_t q[8][4];
    #pragma unroll
    for (int t = 0; t < 8; t++) {
        int ra = (wr + gid)*68 + t*8 + tig;
        q[t][0] = Qs[ra];
        q[t][1] = Qs[ra + 8*68];
        q[t][2] = Qs[ra + 4];
        q[t][3] = Qs[ra + 8*68 + 4];
    }
    __syncthreads();

    CP_WAIT0();
    cvt_pass(0);
    __syncthreads();

    float4 o[8];
    #pragma unroll
    for (int j = 0; j < 8; j++) o[j] = make_float4(0.f, 0.f, 0.f, 0.f);
    float m0r = -1e30f, m1r = -1e30f, l0 = 0.f, l1 = 0.f;

    const int sl0 = (lane & 28) | (tig >> 1);
    const bool odd = (tig & 1);

    #pragma unroll 1
    for (int ci = 0; ci < NCHUNK; ci++) {
        if (ci + 1 < NCHUNK) {
            stage_raw((ci + 1) & 1, (ci + 1) * 64);
            CP_COMMIT();
        }

        // S = Q K^T (Q pre-scaled)
        float4 s[8];
        #pragma unroll
        for (int j = 0; j < 8; j++) s[j] = make_float4(0.f, 0.f, 0.f, 0.f);
        #pragma unroll
        for (int t = 0; t < 8; t++) {
            #pragma unroll
            for (int j = 0; j < 8; j++) {
                int rb = (j*8 + gid)*68 + t*8 + tig;
                mma8(s[j], q[t][0], q[t][1], q[t][2], q[t][3], Ks[rb], Ks[rb + 4]);
            }
        }

        // Online softmax
        float mx0 = -1e30f, mx1 = -1e30f;
        #pragma unroll
        for (int j = 0; j < 8; j++) {
            mx0 = fmaxf(mx0, fmaxf(s[j].x, s[j].y));
            mx1 = fmaxf(mx1, fmaxf(s[j].z, s[j].w));
        }
        mx0 = fmaxf(mx0, __shfl_xor_sync(FULL, mx0, 1));
        mx0 = fmaxf(mx0, __shfl_xor_sync(FULL, mx0, 2));
        mx1 = fmaxf(mx1, __shfl_xor_sync(FULL, mx1, 1));
        mx1 = fmaxf(mx1, __shfl_xor_sync(FULL, mx1, 2));
        float nm0 = fmaxf(m0r, mx0), nm1 = fmaxf(m1r, mx1);
        float al0 = __expf(m0r - nm0), al1 = __expf(m1r - nm1);
        float rs0 = 0.f, rs1 = 0.f;
        #pragma unroll
        for (int j = 0; j < 8; j++) {
            s[j].x = __expf(s[j].x - nm0);
            s[j].y = __expf(s[j].y - nm0);
            s[j].z = __expf(s[j].z - nm1);
            s[j].w = __expf(s[j].w - nm1);
            rs0 += s[j].x + s[j].y;
            rs1 += s[j].z + s[j].w;
        }
        rs0 += __shfl_xor_sync(FULL, rs0, 1);
        rs0 += __shfl_xor_sync(FULL, rs0, 2);
        rs1 += __shfl_xor_sync(FULL, rs1, 1);
        rs1 += __shfl_xor_sync(FULL, rs1, 2);
        l0 = l0*al0 + rs0;  l1 = l1*al1 + rs1;
        m0r = nm0;          m1r = nm1;
        #pragma unroll
        for (int j = 0; j < 8; j++) {
            o[j].x *= al0; o[j].y *= al0; o[j].z *= al1; o[j].w *= al1;
        }

        // O += P @ V : S-accum -> A-fragment conversion via shuffle
        #pragma unroll
        for (int j = 0; j < 8; j++) {
            float x0 = __shfl_sync(FULL, s[j].x, sl0);
            float y0 = __shfl_sync(FULL, s[j].y, sl0);
            float z0 = __shfl_sync(FULL, s[j].z, sl0);
            float w0 = __shfl_sync(FULL, s[j].w, sl0);
            float x1 = __shfl_sync(FULL, s[j].x, sl0 + 2);
            float y1 = __shfl_sync(FULL, s[j].y, sl0 + 2);
            float z1 = __shfl_sync(FULL, s[j].z, sl0 + 2);
            float w1 = __shfl_sync(FULL, s[j].w, sl0 + 2);
            uint32_t a0 = f2tf(odd ? y0 : x0);
            uint32_t a1 = f2tf(odd ? w0 : z0);
            uint32_t a2 = f2tf(odd ? y1 : x1);
            uint32_t a3 = f2tf(odd ? w1 : z1);
            #pragma unroll
            for (int jn = 0; jn < 8; jn++) {
                int rb = (j*8 + tig)*72 + jn*8 + gid;
                mma8(o[jn], a0, a1, a2, a3, Vs[rb], Vs[rb + 4*72]);
            }
        }

        __syncthreads();                      // done reading Ks/Vs
        if (ci + 1 < NCHUNK) {
            CP_WAIT0();                       // chunk c+1 raw landed
            cvt_pass((ci + 1) & 1);           // refresh tf32 K/V
            __syncthreads();
        }
    }

    // Epilogue: ctx[b, s, h*64 + c]
    const int b = bh >> 4, h = bh & 15;
    const float inv0 = 1.f / l0, inv1 = 1.f / l1;
    const int r0 = q0 + wr + gid, r1 = r0 + 8;
    float* c0 = &ctx[((size_t)b*SS + r0)*DM + h*DK];
    float* c1 = &ctx[((size_t)b*SS + r1)*DM + h*DK];
    #pragma unroll
    for (int j = 0; j < 8; j++) {
        int c = j*8 + tig*2;
        *reinterpret_cast<float2*>(&c0[c]) = make_float2(o[j].x*inv0, o[j].y*inv0);
        *reinterpret_cast<float2*>(&c1[c]) = make_float2(o[j].z*inv1, o[j].w*inv1);
    }
}

// ---------------------------------------------------------------------------
extern "C" void kernel_launch(void* const* d_in, const int* in_sizes, int n_in,
                              void* d_out, int out_size) {
    const float* q  = (const float*)d_in[0];
    const float* k  = (const float*)d_in[1];
    const float* v  = (const float*)d_in[2];
    const float* Wq = (const float*)d_in[3];
    const float* Wk = (const float*)d_in[4];
    const float* Wv = (const float*)d_in[5];
    const float* Wo = (const float*)d_in[6];
    const float* bo = (const float*)d_in[7];
    float* out = (float*)d_out;

    float *qh, *kh, *vh, *ctx;
    cudaGetSymbolAddress((void**)&qh,  g_qh);
    cudaGetSymbolAddress((void**)&kh,  g_kh);
    cudaGetSymbolAddress((void**)&vh,  g_vh);
    cudaGetSymbolAddress((void**)&ctx, g_ctx);

    const int proj_smem = (2*A_TILE + 2*B_TILE) * (int)sizeof(float);   // 71680
    const int outp_smem = (4*A_TILE) * (int)sizeof(float);              // 73728
    const int attn_smem = (2*RAW_TILE + 64*68 + 64*72) * (int)sizeof(float); // 101376
    cudaFuncSetAttribute(proj_gemm,    cudaFuncAttributeMaxDynamicSharedMemorySize, proj_smem);
    cudaFuncSetAttribute(outproj_gemm, cudaFuncAttributeMaxDynamicSharedMemorySize, outp_smem);
    cudaFuncSetAttribute(attn4,        cudaFuncAttributeMaxDynamicSharedMemorySize, attn_smem);

    proj_gemm<<<dim3(MTOT/128, DM/128, 3), 256, proj_smem>>>(
        q, k, v, Wq, Wk, Wv, qh, kh, vh);

    attn4<<<dim3(SS/128, BQ*HH), 256, attn_smem>>>(qh, kh, vh, ctx);

    outproj_gemm<<<dim3(MTOT/128, DM/128), 256, outp_smem>>>(ctx, Wo, bo, out);
}

// round 7
// speedup vs baseline: 1.0622x; 1.0622x over previous
#include <cuda_runtime.h>
#include <math.h>
#include <stdint.h>

#define BQ 2
#define HH 16
#define SS 2048
#define DK 64
#define DM 1024
#define MTOT (BQ*SS)   // 4096

// qh/kh/vh hold tf32 bit patterns (qh pre-scaled by 0.125); ctx is fp32
__device__ float g_qh[BQ*HH*SS*DK];
__device__ float g_kh[BQ*HH*SS*DK];
__device__ float g_vh[BQ*HH*SS*DK];
__device__ float g_ctx[BQ*SS*DM];

// ---------------------------------------------------------------------------
__device__ __forceinline__ uint32_t f2tf(float x) {
    uint32_t u;
    asm("cvt.rna.tf32.f32 %0, %1;" : "=r"(u) : "f"(x));
    return u;
}

__device__ __forceinline__ void mma8(float4& d,
                                     uint32_t a0, uint32_t a1, uint32_t a2, uint32_t a3,
                                     uint32_t b0, uint32_t b1) {
    asm volatile(
        "mma.sync.aligned.m16n8k8.row.col.f32.tf32.tf32.f32 "
        "{%0,%1,%2,%3},{%4,%5,%6,%7},{%8,%9},{%0,%1,%2,%3};"
        : "+f"(d.x), "+f"(d.y), "+f"(d.z), "+f"(d.w)
        : "r"(a0), "r"(a1), "r"(a2), "r"(a3), "r"(b0), "r"(b1));
}

__device__ __forceinline__ void cp16g(void* sdst, const void* gsrc) {
    uint32_t sa = (uint32_t)__cvta_generic_to_shared(sdst);
    asm volatile("cp.async.cg.shared.global [%0], [%1], 16;" :: "r"(sa), "l"(gsrc) : "memory");
}
#define CP_COMMIT() asm volatile("cp.async.commit_group;" ::: "memory")
#define CP_WAIT1()  asm volatile("cp.async.wait_group 1;" ::: "memory")
#define CP_WAIT0()  asm volatile("cp.async.wait_group 0;" ::: "memory")

// ---------------------------------------------------------------------------
// Fused QKV projection GEMM. Epilogue now emits tf32 bit patterns
// (Q additionally pre-scaled by 1/sqrt(dk)=0.125, exact).
// ---------------------------------------------------------------------------
#define A_STRIDE 36
#define B_STRIDE 136
#define A_TILE (128*A_STRIDE)
#define B_TILE (32*B_STRIDE)

__global__ __launch_bounds__(256) void proj_gemm(
    const float* __restrict__ Xq, const float* __restrict__ Xk, const float* __restrict__ Xv,
    const float* __restrict__ Wq, const float* __restrict__ Wk, const float* __restrict__ Wv,
    float* __restrict__ Oq, float* __restrict__ Ok, float* __restrict__ Ov)
{
    extern __shared__ float sm[];
    float* As = sm;
    float* Bs = sm + 2*A_TILE;

    const int z = blockIdx.z;
    const float* X = (z == 0) ? Xq : (z == 1) ? Xk : Xv;
    const float* W = (z == 0) ? Wq : (z == 1) ? Wk : Wv;
    float* out     = (z == 0) ? Oq : (z == 1) ? Ok : Ov;
    const float esc = (z == 0) ? 0.125f : 1.0f;

    const int tid = threadIdx.x, lane = tid & 31, warp = tid >> 5;
    const int gid = lane >> 2, tig = lane & 3;
    const int wm = (warp >> 2) * 64, wn = (warp & 3) * 32;
    const int m0 = blockIdx.x * 128, n0 = blockIdx.y * 128;

    float4 acc[4][4];
    #pragma unroll
    for (int i = 0; i < 4; i++)
        #pragma unroll
        for (int j = 0; j < 4; j++) acc[i][j] = make_float4(0.f, 0.f, 0.f, 0.f);

    auto stage = [&](int buf, int k0) {
        float* Ab = As + buf*A_TILE;
        float* Bb = Bs + buf*B_TILE;
        #pragma unroll
        for (int i = 0; i < 4; i++) {
            int f = tid + i*256;
            int r = f >> 3, c = f & 7;
            cp16g(&Ab[r*A_STRIDE + c*4], &X[(size_t)(m0 + r)*DM + k0 + c*4]);
        }
        #pragma unroll
        for (int i = 0; i < 4; i++) {
            int f = tid + i*256;
            int r = f >> 5, c = f & 31;
            int n = n0 + c*4;
            int h = n >> 6, kc = n & 63;
            cp16g(&Bb[r*B_STRIDE + c*4], &W[((size_t)h*DM + k0 + r)*DK + kc]);
        }
    };

    stage(0, 0);  CP_COMMIT();
    stage(1, 32); CP_COMMIT();

    #pragma unroll 1
    for (int k0 = 0; k0 < DM; k0 += 32) {
        int buf = (k0 >> 5) & 1;
        CP_WAIT1();
        __syncthreads();
        const float* Ab = As + buf*A_TILE;
        const float* Bb = Bs + buf*B_TILE;

        #pragma unroll
        for (int kk = 0; kk < 32; kk += 8) {
            uint32_t a[4][4];
            #pragma unroll
            for (int i = 0; i < 4; i++) {
                int ra = (wm + i*16 + gid)*A_STRIDE + kk + tig;
                a[i][0] = f2tf(Ab[ra]);
                a[i][1] = f2tf(Ab[ra + 8*A_STRIDE]);
                a[i][2] = f2tf(Ab[ra + 4]);
                a[i][3] = f2tf(Ab[ra + 8*A_STRIDE + 4]);
            }
            uint32_t b[4][2];
            #pragma unroll
            for (int j = 0; j < 4; j++) {
                int rb = (kk + tig)*B_STRIDE + wn + j*8 + gid;
                b[j][0] = f2tf(Bb[rb]);
                b[j][1] = f2tf(Bb[rb + 4*B_STRIDE]);
            }
            #pragma unroll
            for (int i = 0; i < 4; i++)
                #pragma unroll
                for (int j = 0; j < 4; j++)
                    mma8(acc[i][j], a[i][0], a[i][1], a[i][2], a[i][3], b[j][0], b[j][1]);
        }
        __syncthreads();
        if (k0 + 64 < DM) stage(buf, k0 + 64);
        CP_COMMIT();
    }

    // Epilogue: out[b, h, s, k] as tf32 bit patterns (scaled for Q)
    #pragma unroll
    for (int i = 0; i < 4; i++) {
        int r0 = m0 + wm + i*16 + gid, r1 = r0 + 8;
        int b0i = r0 >> 11, s0 = r0 & 2047;
        int b1i = r1 >> 11, s1 = r1 & 2047;
        #pragma unroll
        for (int j = 0; j < 4; j++) {
            int c = n0 + wn + j*8 + tig*2;
            int h = c >> 6, kc = c & 63;
            *reinterpret_cast<float2*>(&out[(((size_t)b0i*HH + h)*SS + s0)*DK + kc]) =
                make_float2(__uint_as_float(f2tf(acc[i][j].x * esc)),
                            __uint_as_float(f2tf(acc[i][j].y * esc)));
            *reinterpret_cast<float2*>(&out[(((size_t)b1i*HH + h)*SS + s1)*DK + kc]) =
                make_float2(__uint_as_float(f2tf(acc[i][j].z * esc)),
                            __uint_as_float(f2tf(acc[i][j].w * esc)));
        }
    }
}

// ---------------------------------------------------------------------------
// Output projection GEMM (unchanged)
// ---------------------------------------------------------------------------
__global__ __launch_bounds__(256) void outproj_gemm(
    const float* __restrict__ X, const float* __restrict__ Wo,
    const float* __restrict__ bo, float* __restrict__ out)
{
    extern __shared__ float sm[];
    float* As = sm;
    float* Bt = sm + 2*A_TILE;

    const int tid = threadIdx.x, lane = tid & 31, warp = tid >> 5;
    const int gid = lane >> 2, tig = lane & 3;
    const int wm = (warp >> 2) * 64, wn = (warp & 3) * 32;
    const int m0 = blockIdx.x * 128, n0 = blockIdx.y * 128;

    float4 acc[4][4];
    #pragma unroll
    for (int i = 0; i < 4; i++)
        #pragma unroll
        for (int j = 0; j < 4; j++) acc[i][j] = make_float4(0.f, 0.f, 0.f, 0.f);

    auto stage = [&](int buf, int k0) {
        float* Ab = As + buf*A_TILE;
        float* Bb = Bt + buf*A_TILE;
        #pragma unroll
        for (int i = 0; i < 4; i++) {
            int f = tid + i*256;
            int r = f >> 3, c = f & 7;
            cp16g(&Ab[r*A_STRIDE + c*4], &X[(size_t)(m0 + r)*DM + k0 + c*4]);
            cp16g(&Bb[r*A_STRIDE + c*4], &Wo[(size_t)(n0 + r)*DM + k0 + c*4]);
        }
    };

    stage(0, 0);  CP_COMMIT();
    stage(1, 32); CP_COMMIT();

    #pragma unroll 1
    for (int k0 = 0; k0 < DM; k0 += 32) {
        int buf = (k0 >> 5) & 1;
        CP_WAIT1();
        __syncthreads();
        const float* Ab = As + buf*A_TILE;
        const float* Bb = Bt + buf*A_TILE;

        #pragma unroll
        for (int kk = 0; kk < 32; kk += 8) {
            uint32_t a[4][4];
            #pragma unroll
            for (int i = 0; i < 4; i++) {
                int ra = (wm + i*16 + gid)*A_STRIDE + kk + tig;
                a[i][0] = f2tf(Ab[ra]);
                a[i][1] = f2tf(Ab[ra + 8*A_STRIDE]);
                a[i][2] = f2tf(Ab[ra + 4]);
                a[i][3] = f2tf(Ab[ra + 8*A_STRIDE + 4]);
            }
            uint32_t b[4][2];
            #pragma unroll
            for (int j = 0; j < 4; j++) {
                int rb = (wn + j*8 + gid)*A_STRIDE + kk + tig;
                b[j][0] = f2tf(Bb[rb]);
                b[j][1] = f2tf(Bb[rb + 4]);
            }
            #pragma unroll
            for (int i = 0; i < 4; i++)
                #pragma unroll
                for (int j = 0; j < 4; j++)
                    mma8(acc[i][j], a[i][0], a[i][1], a[i][2], a[i][3], b[j][0], b[j][1]);
        }
        __syncthreads();
        if (k0 + 64 < DM) stage(buf, k0 + 64);
        CP_COMMIT();
    }

    #pragma unroll
    for (int i = 0; i < 4; i++) {
        int r0 = m0 + wm + i*16 + gid, r1 = r0 + 8;
        #pragma unroll
        for (int j = 0; j < 4; j++) {
            int c = n0 + wn + j*8 + tig*2;
            float bx = bo[c], by = bo[c + 1];
            *reinterpret_cast<float2*>(&out[(size_t)r0*DM + c]) =
                make_float2(acc[i][j].x + bx, acc[i][j].y + by);
            *reinterpret_cast<float2*>(&out[(size_t)r1*DM + c]) =
                make_float2(acc[i][j].z + bx, acc[i][j].w + by);
        }
    }
}

// ---------------------------------------------------------------------------
// Flash attention v5: K/V arrive pre-converted tf32; cp.async straight into
// the padded Ks/Vs buffers, double-buffered. No conversion work in the loop.
// 128 q-rows/CTA, 64-key chunks, 8 warps.
// ---------------------------------------------------------------------------
#define KV_FLOATS (64*68 + 64*72)   // 8960 per buffer
#define NCHUNK (SS/64)

__global__ __launch_bounds__(256, 2) void attn5(
    const float* __restrict__ Q, const float* __restrict__ K,
    const float* __restrict__ V, float* __restrict__ ctx)
{
    extern __shared__ uint32_t kv[];          // 2 x KV_FLOATS

    const int tid = threadIdx.x, lane = tid & 31, warp = tid >> 5;
    const int gid = lane >> 2, tig = lane & 3;
    const int wr = warp * 16;
    const int q0 = blockIdx.x * 128;
    const int bh = blockIdx.y;
    const unsigned FULL = 0xffffffffu;

    const float* Qb = Q + (size_t)bh * SS * DK;
    const float* Kb = K + (size_t)bh * SS * DK;
    const float* Vb = V + (size_t)bh * SS * DK;

    auto stage_kv = [&](int buf, int j0) {
        uint32_t* Kd = kv + buf*KV_FLOATS;
        uint32_t* Vd = Kd + 64*68;
        #pragma unroll
        for (int i = 0; i < 4; i++) {
            int f = tid + i*256;               // 0..1023
            int r = f >> 4, c4 = f & 15;
            cp16g(&Kd[r*68 + c4*4], &Kb[(size_t)(j0 + r)*DK + c4*4]);
            cp16g(&Vd[r*72 + c4*4], &Vb[(size_t)(j0 + r)*DK + c4*4]);
        }
    };

    // Prologue: chunk-0 K/V into buf 0; Q into buf 1 (reused after lift).
    stage_kv(0, 0);
    uint32_t* Qs = kv + KV_FLOATS;             // 128*68 = 8704 <= 8960
    #pragma unroll
    for (int i = 0; i < 8; i++) {
        int f = tid + i*256;                   // 0..2047
        int r = f >> 4, c4 = f & 15;
        cp16g(&Qs[r*68 + c4*4], &Qb[(size_t)(q0 + r)*DK + c4*4]);
    }
    CP_COMMIT();
    CP_WAIT0();
    __syncthreads();

    uint32_t q[8][4];
    #pragma unroll
    for (int t = 0; t < 8; t++) {
        int ra = (wr + gid)*68 + t*8 + tig;
        q[t][0] = Qs[ra];
        q[t][1] = Qs[ra + 8*68];
        q[t][2] = Qs[ra + 4];
        q[t][3] = Qs[ra + 8*68 + 4];
    }
    __syncthreads();                           // Q lifted; buf 1 reusable

    float4 o[8];
    #pragma unroll
    for (int j = 0; j < 8; j++) o[j] = make_float4(0.f, 0.f, 0.f, 0.f);
    float m0r = -1e30f, m1r = -1e30f, l0 = 0.f, l1 = 0.f;

    const int sl0 = (lane & 28) | (tig >> 1);
    const bool odd = (tig & 1);

    #pragma unroll 1
    for (int ci = 0; ci < NCHUNK; ci++) {
        const int buf = ci & 1;
        if (ci + 1 < NCHUNK) {
            stage_kv(buf ^ 1, (ci + 1) * 64);
            CP_COMMIT();
        }
        const uint32_t* Ks = kv + buf*KV_FLOATS;
        const uint32_t* Vs = Ks + 64*68;

        // S = Q K^T (Q pre-scaled at projection time)
        float4 s[8];
        #pragma unroll
        for (int j = 0; j < 8; j++) s[j] = make_float4(0.f, 0.f, 0.f, 0.f);
        #pragma unroll
        for (int t = 0; t < 8; t++) {
            #pragma unroll
            for (int j = 0; j < 8; j++) {
                int rb = (j*8 + gid)*68 + t*8 + tig;
                mma8(s[j], q[t][0], q[t][1], q[t][2], q[t][3], Ks[rb], Ks[rb + 4]);
            }
        }

        // Online softmax
        float mx0 = -1e30f, mx1 = -1e30f;
        #pragma unroll
        for (int j = 0; j < 8; j++) {
            mx0 = fmaxf(mx0, fmaxf(s[j].x, s[j].y));
            mx1 = fmaxf(mx1, fmaxf(s[j].z, s[j].w));
        }
        mx0 = fmaxf(mx0, __shfl_xor_sync(FULL, mx0, 1));
        mx0 = fmaxf(mx0, __shfl_xor_sync(FULL, mx0, 2));
        mx1 = fmaxf(mx1, __shfl_xor_sync(FULL, mx1, 1));
        mx1 = fmaxf(mx1, __shfl_xor_sync(FULL, mx1, 2));
        float nm0 = fmaxf(m0r, mx0), nm1 = fmaxf(m1r, mx1);
        float al0 = __expf(m0r - nm0), al1 = __expf(m1r - nm1);
        float rs0 = 0.f, rs1 = 0.f;
        #pragma unroll
        for (int j = 0; j < 8; j++) {
            s[j].x = __expf(s[j].x - nm0);
            s[j].y = __expf(s[j].y - nm0);
            s[j].z = __expf(s[j].z - nm1);
            s[j].w = __expf(s[j].w - nm1);
            rs0 += s[j].x + s[j].y;
            rs1 += s[j].z + s[j].w;
        }
        rs0 += __shfl_xor_sync(FULL, rs0, 1);
        rs0 += __shfl_xor_sync(FULL, rs0, 2);
        rs1 += __shfl_xor_sync(FULL, rs1, 1);
        rs1 += __shfl_xor_sync(FULL, rs1, 2);
        l0 = l0*al0 + rs0;  l1 = l1*al1 + rs1;
        m0r = nm0;          m1r = nm1;
        #pragma unroll
        for (int j = 0; j < 8; j++) {
            o[j].x *= al0; o[j].y *= al0; o[j].z *= al1; o[j].w *= al1;
        }

        // O += P @ V : S-accum -> A-fragment conversion via shuffle
        #pragma unroll
        for (int j = 0; j < 8; j++) {
            float x0 = __shfl_sync(FULL, s[j].x, sl0);
            float y0 = __shfl_sync(FULL, s[j].y, sl0);
            float z0 = __shfl_sync(FULL, s[j].z, sl0);
            float w0 = __shfl_sync(FULL, s[j].w, sl0);
            float x1 = __shfl_sync(FULL, s[j].x, sl0 + 2);
            float y1 = __shfl_sync(FULL, s[j].y, sl0 + 2);
            float z1 = __shfl_sync(FULL, s[j].z, sl0 + 2);
            float w1 = __shfl_sync(FULL, s[j].w, sl0 + 2);
            uint32_t a0 = f2tf(odd ? y0 : x0);
            uint32_t a1 = f2tf(odd ? w0 : z0);
            uint32_t a2 = f2tf(odd ? y1 : x1);
            uint32_t a3 = f2tf(odd ? w1 : z1);
            #pragma unroll
            for (int jn = 0; jn < 8; jn++) {
                int rb = (j*8 + tig)*72 + jn*8 + gid;
                mma8(o[jn], a0, a1, a2, a3, Vs[rb], Vs[rb + 4*72]);
            }
        }

        if (ci + 1 < NCHUNK) CP_WAIT0();       // next chunk landed
        __syncthreads();                        // all warps done with buf; data visible
    }

    // Epilogue: ctx[b, s, h*64 + c]
    const int b = bh >> 4, h = bh & 15;
    const float inv0 = 1.f / l0, inv1 = 1.f / l1;
    const int r0 = q0 + wr + gid, r1 = r0 + 8;
    float* c0 = &ctx[((size_t)b*SS + r0)*DM + h*DK];
    float* c1 = &ctx[((size_t)b*SS + r1)*DM + h*DK];
    #pragma unroll
    for (int j = 0; j < 8; j++) {
        int c = j*8 + tig*2;
        *reinterpret_cast<float2*>(&c0[c]) = make_float2(o[j].x*inv0, o[j].y*inv0);
        *reinterpret_cast<float2*>(&c1[c]) = make_float2(o[j].z*inv1, o[j].w*inv1);
    }
}

// ---------------------------------------------------------------------------
extern "C" void kernel_launch(void* const* d_in, const int* in_sizes, int n_in,
                              void* d_out, int out_size) {
    const float* q  = (const float*)d_in[0];
    const float* k  = (const float*)d_in[1];
    const float* v  = (const float*)d_in[2];
    const float* Wq = (const float*)d_in[3];
    const float* Wk = (const float*)d_in[4];
    const float* Wv = (const float*)d_in[5];
    const float* Wo = (const float*)d_in[6];
    const float* bo = (const float*)d_in[7];
    float* out = (float*)d_out;

    float *qh, *kh, *vh, *ctx;
    cudaGetSymbolAddress((void**)&qh,  g_qh);
    cudaGetSymbolAddress((void**)&kh,  g_kh);
    cudaGetSymbolAddress((void**)&vh,  g_vh);
    cudaGetSymbolAddress((void**)&ctx, g_ctx);

    const int proj_smem = (2*A_TILE + 2*B_TILE) * (int)sizeof(float);   // 71680
    const int outp_smem = (4*A_TILE) * (int)sizeof(float);              // 73728
    const int attn_smem = (2*KV_FLOATS) * (int)sizeof(uint32_t);        // 71680
    cudaFuncSetAttribute(proj_gemm,    cudaFuncAttributeMaxDynamicSharedMemorySize, proj_smem);
    cudaFuncSetAttribute(outproj_gemm, cudaFuncAttributeMaxDynamicSharedMemorySize, outp_smem);
    cudaFuncSetAttribute(attn5,        cudaFuncAttributeMaxDynamicSharedMemorySize, attn_smem);

    proj_gemm<<<dim3(MTOT/128, DM/128, 3), 256, proj_smem>>>(
        q, k, v, Wq, Wk, Wv, qh, kh, vh);

    attn5<<<dim3(SS/128, BQ*HH), 256, attn_smem>>>(qh, kh, vh, ctx);

    outproj_gemm<<<dim3(MTOT/128, DM/128), 256, outp_smem>>>(ctx, Wo, bo, out);
}

// round 8
// speedup vs baseline: 1.0669x; 1.0044x over previous
#include <cuda_runtime.h>
#include <math.h>
#include <stdint.h>

#define BQ 2
#define HH 16
#define SS 2048
#define DK 64
#define DM 1024
#define MTOT (BQ*SS)   // 4096

// qh/kh/vh hold tf32 bit patterns (qh pre-scaled by 0.125); ctx is fp32
__device__ float g_qh[BQ*HH*SS*DK];
__device__ float g_kh[BQ*HH*SS*DK];
__device__ float g_vh[BQ*HH*SS*DK];
__device__ float g_ctx[BQ*SS*DM];

// ---------------------------------------------------------------------------
__device__ __forceinline__ uint32_t f2tf(float x) {
    uint32_t u;
    asm("cvt.rna.tf32.f32 %0, %1;" : "=r"(u) : "f"(x));
    return u;
}

__device__ __forceinline__ void mma8(float4& d,
                                     uint32_t a0, uint32_t a1, uint32_t a2, uint32_t a3,
                                     uint32_t b0, uint32_t b1) {
    asm volatile(
        "mma.sync.aligned.m16n8k8.row.col.f32.tf32.tf32.f32 "
        "{%0,%1,%2,%3},{%4,%5,%6,%7},{%8,%9},{%0,%1,%2,%3};"
        : "+f"(d.x), "+f"(d.y), "+f"(d.z), "+f"(d.w)
        : "r"(a0), "r"(a1), "r"(a2), "r"(a3), "r"(b0), "r"(b1));
}

__device__ __forceinline__ void cp16g(void* sdst, const void* gsrc) {
    uint32_t sa = (uint32_t)__cvta_generic_to_shared(sdst);
    asm volatile("cp.async.cg.shared.global [%0], [%1], 16;" :: "r"(sa), "l"(gsrc) : "memory");
}
#define CP_COMMIT() asm volatile("cp.async.commit_group;" ::: "memory")
#define CP_WAIT1()  asm volatile("cp.async.wait_group 1;" ::: "memory")
#define CP_WAIT0()  asm volatile("cp.async.wait_group 0;" ::: "memory")

// ---------------------------------------------------------------------------
// Fused QKV projection GEMM. Epilogue now emits tf32 bit patterns
// (Q additionally pre-scaled by 1/sqrt(dk)=0.125, exact).
// ---------------------------------------------------------------------------
#define A_STRIDE 36
#define B_STRIDE 136
#define A_TILE (128*A_STRIDE)
#define B_TILE (32*B_STRIDE)

__global__ __launch_bounds__(256) void proj_gemm(
    const float* __restrict__ Xq, const float* __restrict__ Xk, const float* __restrict__ Xv,
    const float* __restrict__ Wq, const float* __restrict__ Wk, const float* __restrict__ Wv,
    float* __restrict__ Oq, float* __restrict__ Ok, float* __restrict__ Ov)
{
    extern __shared__ float sm[];
    float* As = sm;
    float* Bs = sm + 2*A_TILE;

    const int z = blockIdx.z;
    const float* X = (z == 0) ? Xq : (z == 1) ? Xk : Xv;
    const float* W = (z == 0) ? Wq : (z == 1) ? Wk : Wv;
    float* out     = (z == 0) ? Oq : (z == 1) ? Ok : Ov;
    const float esc = (z == 0) ? 0.125f : 1.0f;

    const int tid = threadIdx.x, lane = tid & 31, warp = tid >> 5;
    const int gid = lane >> 2, tig = lane & 3;
    const int wm = (warp >> 2) * 64, wn = (warp & 3) * 32;
    const int m0 = blockIdx.x * 128, n0 = blockIdx.y * 128;

    float4 acc[4][4];
    #pragma unroll
    for (int i = 0; i < 4; i++)
        #pragma unroll
        for (int j = 0; j < 4; j++) acc[i][j] = make_float4(0.f, 0.f, 0.f, 0.f);

    auto stage = [&](int buf, int k0) {
        float* Ab = As + buf*A_TILE;
        float* Bb = Bs + buf*B_TILE;
        #pragma unroll
        for (int i = 0; i < 4; i++) {
            int f = tid + i*256;
            int r = f >> 3, c = f & 7;
            cp16g(&Ab[r*A_STRIDE + c*4], &X[(size_t)(m0 + r)*DM + k0 + c*4]);
        }
        #pragma unroll
        for (int i = 0; i < 4; i++) {
            int f = tid + i*256;
            int r = f >> 5, c = f & 31;
            int n = n0 + c*4;
            int h = n >> 6, kc = n & 63;
            cp16g(&Bb[r*B_STRIDE + c*4], &W[((size_t)h*DM + k0 + r)*DK + kc]);
        }
    };

    stage(0, 0);  CP_COMMIT();
    stage(1, 32); CP_COMMIT();

    #pragma unroll 1
    for (int k0 = 0; k0 < DM; k0 += 32) {
        int buf = (k0 >> 5) & 1;
        CP_WAIT1();
        __syncthreads();
        const float* Ab = As + buf*A_TILE;
        const float* Bb = Bs + buf*B_TILE;

        #pragma unroll
        for (int kk = 0; kk < 32; kk += 8) {
            uint32_t a[4][4];
            #pragma unroll
            for (int i = 0; i < 4; i++) {
                int ra = (wm + i*16 + gid)*A_STRIDE + kk + tig;
                a[i][0] = f2tf(Ab[ra]);
                a[i][1] = f2tf(Ab[ra + 8*A_STRIDE]);
                a[i][2] = f2tf(Ab[ra + 4]);
                a[i][3] = f2tf(Ab[ra + 8*A_STRIDE + 4]);
            }
            uint32_t b[4][2];
            #pragma unroll
            for (int j = 0; j < 4; j++) {
                int rb = (kk + tig)*B_STRIDE + wn + j*8 + gid;
                b[j][0] = f2tf(Bb[rb]);
                b[j][1] = f2tf(Bb[rb + 4*B_STRIDE]);
            }
            #pragma unroll
            for (int i = 0; i < 4; i++)
                #pragma unroll
                for (int j = 0; j < 4; j++)
                    mma8(acc[i][j], a[i][0], a[i][1], a[i][2], a[i][3], b[j][0], b[j][1]);
        }
        __syncthreads();
        if (k0 + 64 < DM) stage(buf, k0 + 64);
        CP_COMMIT();
    }

    // Epilogue: out[b, h, s, k] as tf32 bit patterns (scaled for Q)
    #pragma unroll
    for (int i = 0; i < 4; i++) {
        int r0 = m0 + wm + i*16 + gid, r1 = r0 + 8;
        int b0i = r0 >> 11, s0 = r0 & 2047;
        int b1i = r1 >> 11, s1 = r1 & 2047;
        #pragma unroll
        for (int j = 0; j < 4; j++) {
            int c = n0 + wn + j*8 + tig*2;
            int h = c >> 6, kc = c & 63;
            *reinterpret_cast<float2*>(&out[(((size_t)b0i*HH + h)*SS + s0)*DK + kc]) =
                make_float2(__uint_as_float(f2tf(acc[i][j].x * esc)),
                            __uint_as_float(f2tf(acc[i][j].y * esc)));
            *reinterpret_cast<float2*>(&out[(((size_t)b1i*HH + h)*SS + s1)*DK + kc]) =
                make_float2(__uint_as_float(f2tf(acc[i][j].z * esc)),
                            __uint_as_float(f2tf(acc[i][j].w * esc)));
        }
    }
}

// ---------------------------------------------------------------------------
// Output projection GEMM (unchanged)
// ---------------------------------------------------------------------------
__global__ __launch_bounds__(256) void outproj_gemm(
    const float* __restrict__ X, const float* __restrict__ Wo,
    const float* __restrict__ bo, float* __restrict__ out)
{
    extern __shared__ float sm[];
    float* As = sm;
    float* Bt = sm + 2*A_TILE;

    const int tid = threadIdx.x, lane = tid & 31, warp = tid >> 5;
    const int gid = lane >> 2, tig = lane & 3;
    const int wm = (warp >> 2) * 64, wn = (warp & 3) * 32;
    const int m0 = blockIdx.x * 128, n0 = blockIdx.y * 128;

    float4 acc[4][4];
    #pragma unroll
    for (int i = 0; i < 4; i++)
        #pragma unroll
        for (int j = 0; j < 4; j++) acc[i][j] = make_float4(0.f, 0.f, 0.f, 0.f);

    auto stage = [&](int buf, int k0) {
        float* Ab = As + buf*A_TILE;
        float* Bb = Bt + buf*A_TILE;
        #pragma unroll
        for (int i = 0; i < 4; i++) {
            int f = tid + i*256;
            int r = f >> 3, c = f & 7;
            cp16g(&Ab[r*A_STRIDE + c*4], &X[(size_t)(m0 + r)*DM + k0 + c*4]);
            cp16g(&Bb[r*A_STRIDE + c*4], &Wo[(size_t)(n0 + r)*DM + k0 + c*4]);
        }
    };

    stage(0, 0);  CP_COMMIT();
    stage(1, 32); CP_COMMIT();

    #pragma unroll 1
    for (int k0 = 0; k0 < DM; k0 += 32) {
        int buf = (k0 >> 5) & 1;
        CP_WAIT1();
        __syncthreads();
        const float* Ab = As + buf*A_TILE;
        const float* Bb = Bt + buf*A_TILE;

        #pragma unroll
        for (int kk = 0; kk < 32; kk += 8) {
            uint32_t a[4][4];
            #pragma unroll
            for (int i = 0; i < 4; i++) {
                int ra = (wm + i*16 + gid)*A_STRIDE + kk + tig;
                a[i][0] = f2tf(Ab[ra]);
                a[i][1] = f2tf(Ab[ra + 8*A_STRIDE]);
                a[i][2] = f2tf(Ab[ra + 4]);
                a[i][3] = f2tf(Ab[ra + 8*A_STRIDE + 4]);
            }
            uint32_t b[4][2];
            #pragma unroll
            for (int j = 0; j < 4; j++) {
                int rb = (wn + j*8 + gid)*A_STRIDE + kk + tig;
                b[j][0] = f2tf(Bb[rb]);
                b[j][1] = f2tf(Bb[rb + 4]);
            }
            #pragma unroll
            for (int i = 0; i < 4; i++)
                #pragma unroll
                for (int j = 0; j < 4; j++)
                    mma8(acc[i][j], a[i][0], a[i][1], a[i][2], a[i][3], b[j][0], b[j][1]);
        }
        __syncthreads();
        if (k0 + 64 < DM) stage(buf, k0 + 64);
        CP_COMMIT();
    }

    #pragma unroll
    for (int i = 0; i < 4; i++) {
        int r0 = m0 + wm + i*16 + gid, r1 = r0 + 8;
        #pragma unroll
        for (int j = 0; j < 4; j++) {
            int c = n0 + wn + j*8 + tig*2;
            float bx = bo[c], by = bo[c + 1];
            *reinterpret_cast<float2*>(&out[(size_t)r0*DM + c]) =
                make_float2(acc[i][j].x + bx, acc[i][j].y + by);
            *reinterpret_cast<float2*>(&out[(size_t)r1*DM + c]) =
                make_float2(acc[i][j].z + bx, acc[i][j].w + by);
        }
    }
}

// ---------------------------------------------------------------------------
// Flash attention v5: K/V arrive pre-converted tf32; cp.async straight into
// the padded Ks/Vs buffers, double-buffered. No conversion work in the loop.
// 128 q-rows/CTA, 64-key chunks, 8 warps.
// ---------------------------------------------------------------------------
#define KV_FLOATS (64*68 + 64*72)   // 8960 per buffer
#define NCHUNK (SS/64)

__global__ __launch_bounds__(256, 2) void attn5(
    const float* __restrict__ Q, const float* __restrict__ K,
    const float* __restrict__ V, float* __restrict__ ctx)
{
    extern __shared__ uint32_t kv[];          // 2 x KV_FLOATS

    const int tid = threadIdx.x, lane = tid & 31, warp = tid >> 5;
    const int gid = lane >> 2, tig = lane & 3;
    const int wr = warp * 16;
    const int q0 = blockIdx.x * 128;
    const int bh = blockIdx.y;
    const unsigned FULL = 0xffffffffu;

    const float* Qb = Q + (size_t)bh * SS * DK;
    const float* Kb = K + (size_t)bh * SS * DK;
    const float* Vb = V + (size_t)bh * SS * DK;

    auto stage_kv = [&](int buf, int j0) {
        uint32_t* Kd = kv + buf*KV_FLOATS;
        uint32_t* Vd = Kd + 64*68;
        #pragma unroll
        for (int i = 0; i < 4; i++) {
            int f = tid + i*256;               // 0..1023
            int r = f >> 4, c4 = f & 15;
            cp16g(&Kd[r*68 + c4*4], &Kb[(size_t)(j0 + r)*DK + c4*4]);
            cp16g(&Vd[r*72 + c4*4], &Vb[(size_t)(j0 + r)*DK + c4*4]);
        }
    };

    // Prologue: chunk-0 K/V into buf 0; Q into buf 1 (reused after lift).
    stage_kv(0, 0);
    uint32_t* Qs = kv + KV_FLOATS;             // 128*68 = 8704 <= 8960
    #pragma unroll
    for (int i = 0; i < 8; i++) {
        int f = tid + i*256;                   // 0..2047
        int r = f >> 4, c4 = f & 15;
        cp16g(&Qs[r*68 + c4*4], &Qb[(size_t)(q0 + r)*DK + c4*4]);
    }
    CP_COMMIT();
    CP_WAIT0();
    __syncthreads();

    uint32_t q[8][4];
    #pragma unroll
    for (int t = 0; t < 8; t++) {
        int ra = (wr + gid)*68 + t*8 + tig;
        q[t][0] = Qs[ra];
        q[t][1] = Qs[ra + 8*68];
        q[t][2] = Qs[ra + 4];
        q[t][3] = Qs[ra + 8*68 + 4];
    }
    __syncthreads();                           // Q lifted; buf 1 reusable

    float4 o[8];
    #pragma unroll
    for (int j = 0; j < 8; j++) o[j] = make_float4(0.f, 0.f, 0.f, 0.f);
    float m0r = -1e30f, m1r = -1e30f, l0 = 0.f, l1 = 0.f;

    const int sl0 = (lane & 28) | (tig >> 1);
    const bool odd = (tig & 1);

    #pragma unroll 1
    for (int ci = 0; ci < NCHUNK; ci++) {
        const int buf = ci & 1;
        if (ci + 1 < NCHUNK) {
            stage_kv(buf ^ 1, (ci + 1) * 64);
            CP_COMMIT();
        }
        const uint32_t* Ks = kv + buf*KV_FLOATS;
        const uint32_t* Vs = Ks + 64*68;

        // S = Q K^T (Q pre-scaled at projection time)
        float4 s[8];
        #pragma unroll
        for (int j = 0; j < 8; j++) s[j] = make_float4(0.f, 0.f, 0.f, 0.f);
        #pragma unroll
        for (int t = 0; t < 8; t++) {
            #pragma unroll
            for (int j = 0; j < 8; j++) {
                int rb = (j*8 + gid)*68 + t*8 + tig;
                mma8(s[j], q[t][0], q[t][1], q[t][2], q[t][3], Ks[rb], Ks[rb + 4]);
            }
        }

        // Online softmax
        float mx0 = -1e30f, mx1 = -1e30f;
        #pragma unroll
        for (int j = 0; j < 8; j++) {
            mx0 = fmaxf(mx0, fmaxf(s[j].x, s[j].y));
            mx1 = fmaxf(mx1, fmaxf(s[j].z, s[j].w));
        }
        mx0 = fmaxf(mx0, __shfl_xor_sync(FULL, mx0, 1));
        mx0 = fmaxf(mx0, __shfl_xor_sync(FULL, mx0, 2));
        mx1 = fmaxf(mx1, __shfl_xor_sync(FULL, mx1, 1));
        mx1 = fmaxf(mx1, __shfl_xor_sync(FULL, mx1, 2));
        float nm0 = fmaxf(m0r, mx0), nm1 = fmaxf(m1r, mx1);
        float al0 = __expf(m0r - nm0), al1 = __expf(m1r - nm1);
        float rs0 = 0.f, rs1 = 0.f;
        #pragma unroll
        for (int j = 0; j < 8; j++) {
            s[j].x = __expf(s[j].x - nm0);
            s[j].y = __expf(s[j].y - nm0);
            s[j].z = __expf(s[j].z - nm1);
            s[j].w = __expf(s[j].w - nm1);
            rs0 += s[j].x + s[j].y;
            rs1 += s[j].z + s[j].w;
        }
        rs0 += __shfl_xor_sync(FULL, rs0, 1);
        rs0 += __shfl_xor_sync(FULL, rs0, 2);
        rs1 += __shfl_xor_sync(FULL, rs1, 1);
        rs1 += __shfl_xor_sync(FULL, rs1, 2);
        l0 = l0*al0 + rs0;  l1 = l1*al1 + rs1;
        m0r = nm0;          m1r = nm1;
        #pragma unroll
        for (int j = 0; j < 8; j++) {
            o[j].x *= al0; o[j].y *= al0; o[j].z *= al1; o[j].w *= al1;
        }

        // O += P @ V : S-accum -> A-fragment conversion via shuffle
        #pragma unroll
        for (int j = 0; j < 8; j++) {
            float x0 = __shfl_sync(FULL, s[j].x, sl0);
            float y0 = __shfl_sync(FULL, s[j].y, sl0);
            float z0 = __shfl_sync(FULL, s[j].z, sl0);
            float w0 = __shfl_sync(FULL, s[j].w, sl0);
            float x1 = __shfl_sync(FULL, s[j].x, sl0 + 2);
            float y1 = __shfl_sync(FULL, s[j].y, sl0 + 2);
            float z1 = __shfl_sync(FULL, s[j].z, sl0 + 2);
            float w1 = __shfl_sync(FULL, s[j].w, sl0 + 2);
            uint32_t a0 = f2tf(odd ? y0 : x0);
            uint32_t a1 = f2tf(odd ? w0 : z0);
            uint32_t a2 = f2tf(odd ? y1 : x1);
            uint32_t a3 = f2tf(odd ? w1 : z1);
            #pragma unroll
            for (int jn = 0; jn < 8; jn++) {
                int rb = (j*8 + tig)*72 + jn*8 + gid;
                mma8(o[jn], a0, a1, a2, a3, Vs[rb], Vs[rb + 4*72]);
            }
        }

        if (ci + 1 < NCHUNK) CP_WAIT0();       // next chunk landed
        __syncthreads();                        // all warps done with buf; data visible
    }

    // Epilogue: ctx[b, s, h*64 + c]
    const int b = bh >> 4, h = bh & 15;
    const float inv0 = 1.f / l0, inv1 = 1.f / l1;
    const int r0 = q0 + wr + gid, r1 = r0 + 8;
    float* c0 = &ctx[((size_t)b*SS + r0)*DM + h*DK];
    float* c1 = &ctx[((size_t)b*SS + r1)*DM + h*DK];
    #pragma unroll
    for (int j = 0; j < 8; j++) {
        int c = j*8 + tig*2;
        *reinterpret_cast<float2*>(&c0[c]) = make_float2(o[j].x*inv0, o[j].y*inv0);
        *reinterpret_cast<float2*>(&c1[c]) = make_float2(o[j].z*inv1, o[j].w*inv1);
    }
}

// ---------------------------------------------------------------------------
extern "C" void kernel_launch(void* const* d_in, const int* in_sizes, int n_in,
                              void* d_out, int out_size) {
    const float* q  = (const float*)d_in[0];
    const float* k  = (const float*)d_in[1];
    const float* v  = (const float*)d_in[2];
    const float* Wq = (const float*)d_in[3];
    const float* Wk = (const float*)d_in[4];
    const float* Wv = (const float*)d_in[5];
    const float* Wo = (const float*)d_in[6];
    const float* bo = (const float*)d_in[7];
    float* out = (float*)d_out;

    float *qh, *kh, *vh, *ctx;
    cudaGetSymbolAddress((void**)&qh,  g_qh);
    cudaGetSymbolAddress((void**)&kh,  g_kh);
    cudaGetSymbolAddress((void**)&vh,  g_vh);
    cudaGetSymbolAddress((void**)&ctx, g_ctx);

    const int proj_smem = (2*A_TILE + 2*B_TILE) * (int)sizeof(float);   // 71680
    const int outp_smem = (4*A_TILE) * (int)sizeof(float);              // 73728
    const int attn_smem = (2*KV_FLOATS) * (int)sizeof(uint32_t);        // 71680
    cudaFuncSetAttribute(proj_gemm,    cudaFuncAttributeMaxDynamicSharedMemorySize, proj_smem);
    cudaFuncSetAttribute(outproj_gemm, cudaFuncAttributeMaxDynamicSharedMemorySize, outp_smem);
    cudaFuncSetAttribute(attn5,        cudaFuncAttributeMaxDynamicSharedMemorySize, attn_smem);

    proj_gemm<<<dim3(MTOT/128, DM/128, 3), 256, proj_smem>>>(
        q, k, v, Wq, Wk, Wv, qh, kh, vh);

    attn5<<<dim3(SS/128, BQ*HH), 256, attn_smem>>>(qh, kh, vh, ctx);

    outproj_gemm<<<dim3(MTOT/128, DM/128), 256, outp_smem>>>(ctx, Wo, bo, out);
}